// round 1
// baseline (speedup 1.0000x reference)
#include <cuda_runtime.h>
#include <cuda_bf16.h>
#include <cstdint>

#define N_NODES 10000
#define N_EDGES 640000
#define D_FEAT  128

// Scratch for the aggregated (segment-summed) edge features. Device global:
// no allocations allowed in kernel_launch.
__device__ __align__(16) float g_agg[N_NODES * D_FEAT];

// ---------------------------------------------------------------------------
// Kernel 1: zero the aggregation buffer (vectorized).
// ---------------------------------------------------------------------------
__global__ void zero_agg_kernel() {
    int i = blockIdx.x * blockDim.x + threadIdx.x;
    const int n4 = N_NODES * D_FEAT / 4;
    float4* p = reinterpret_cast<float4*>(g_agg);
    if (i < n4) p[i] = make_float4(0.f, 0.f, 0.f, 0.f);
}

// ---------------------------------------------------------------------------
// Kernel 2: scatter-add edge features into receiver nodes.
// One warp per edge; each lane handles a float4 (32 lanes x 4 = 128 feats).
// Uses red.global.add.v4.f32 (sm_90+) so 128 floats cost 32 RED instrs, not 128.
// ---------------------------------------------------------------------------
__global__ void scatter_kernel(const float* __restrict__ edge_feat,
                               const int*   __restrict__ recv_idx) {
    int gtid = blockIdx.x * blockDim.x + threadIdx.x;
    int edge = gtid >> 5;
    int lane = gtid & 31;
    if (edge >= N_EDGES) return;

    int node = __ldg(&recv_idx[edge]);
    const float4 v = *reinterpret_cast<const float4*>(
        edge_feat + (size_t)edge * D_FEAT + lane * 4);
    float* dst = g_agg + (size_t)node * D_FEAT + lane * 4;
    asm volatile("red.global.add.v4.f32 [%0], {%1, %2, %3, %4};"
                 :: "l"(dst), "f"(v.x), "f"(v.y), "f"(v.z), "f"(v.w)
                 : "memory");
}

// ---------------------------------------------------------------------------
// Kernel 3: out = [node_feat | agg] @ W + b
// Tiled fp32 GEMM. Block: 256 threads, computes a 64-node x 128-col tile.
// Each thread: 8 nodes x 4 cols = 32 accumulators.
// K is tiled in chunks of 32; W chunk (32x128) and X chunk (64x32) staged in smem.
// The "concat" is virtual: k < 128 reads node_feat, k >= 128 reads g_agg.
// ---------------------------------------------------------------------------
#define NT 64
#define KC 32

__global__ __launch_bounds__(256) void gemm_kernel(
    const float* __restrict__ node_feat,
    const float* __restrict__ W,     // [2*D_FEAT, D_FEAT] row-major
    const float* __restrict__ b,     // [D_FEAT]
    float* __restrict__ out)         // [N_NODES, D_FEAT]
{
    __shared__ float Ws[KC * D_FEAT];   // 16 KB, chunk of W rows
    __shared__ float Xs[NT * KC];       // 8 KB, chunk of collected features

    const int tid  = threadIdx.x;
    const int lane = tid & 31;          // -> output column group (lane*4)
    const int wid  = tid >> 5;          // -> node subgroup (wid*8)
    const int n0   = blockIdx.x * NT;

    float acc[8][4];
    #pragma unroll
    for (int i = 0; i < 8; i++)
        #pragma unroll
        for (int j = 0; j < 4; j++) acc[i][j] = 0.f;

    for (int k0 = 0; k0 < 2 * D_FEAT; k0 += KC) {
        // Stage W[k0:k0+KC, :] -> Ws (vectorized, coalesced)
        {
            const float4* src = reinterpret_cast<const float4*>(W + k0 * D_FEAT);
            float4* dst = reinterpret_cast<float4*>(Ws);
            #pragma unroll
            for (int i = 0; i < (KC * D_FEAT / 4) / 256; i++)
                dst[tid + i * 256] = src[tid + i * 256];
        }
        // Stage X tile: Xs[n][k] = collected[n0+n, k0+k]
        #pragma unroll
        for (int i = tid; i < NT * KC; i += 256) {
            int n  = i >> 5;          // / KC
            int k  = i & (KC - 1);    // % KC
            int gn = n0 + n;
            int gk = k0 + k;
            float v = 0.f;
            if (gn < N_NODES) {
                v = (gk < D_FEAT) ? __ldg(&node_feat[(size_t)gn * D_FEAT + gk])
                                  : g_agg[(size_t)gn * D_FEAT + (gk - D_FEAT)];
            }
            Xs[i] = v;
        }
        __syncthreads();

        #pragma unroll
        for (int kk = 0; kk < KC; kk++) {
            float4 w = *reinterpret_cast<const float4*>(&Ws[kk * D_FEAT + lane * 4]);
            #pragma unroll
            for (int n = 0; n < 8; n++) {
                float x = Xs[(wid * 8 + n) * KC + kk];   // broadcast within warp
                acc[n][0] = fmaf(x, w.x, acc[n][0]);
                acc[n][1] = fmaf(x, w.y, acc[n][1]);
                acc[n][2] = fmaf(x, w.z, acc[n][2]);
                acc[n][3] = fmaf(x, w.w, acc[n][3]);
            }
        }
        __syncthreads();
    }

    // Epilogue: add bias, store float4 per (node, col-group)
    float4 bb = *reinterpret_cast<const float4*>(&b[lane * 4]);
    #pragma unroll
    for (int n = 0; n < 8; n++) {
        int gn = n0 + wid * 8 + n;
        if (gn < N_NODES) {
            float4 r;
            r.x = acc[n][0] + bb.x;
            r.y = acc[n][1] + bb.y;
            r.z = acc[n][2] + bb.z;
            r.w = acc[n][3] + bb.w;
            *reinterpret_cast<float4*>(out + (size_t)gn * D_FEAT + lane * 4) = r;
        }
    }
}

// ---------------------------------------------------------------------------
extern "C" void kernel_launch(void* const* d_in, const int* in_sizes, int n_in,
                              void* d_out, int out_size) {
    const float* edge_feat = (const float*)d_in[0];
    const float* node_feat = (const float*)d_in[1];
    const int*   recv_idx  = (const int*)d_in[2];
    const float* W         = (const float*)d_in[3];
    const float* b         = (const float*)d_in[4];
    float*       out       = (float*)d_out;

    // 1. zero agg
    {
        int n4 = N_NODES * D_FEAT / 4;
        zero_agg_kernel<<<(n4 + 255) / 256, 256>>>();
    }
    // 2. scatter-add (one warp per edge)
    {
        long long threads = (long long)N_EDGES * 32;
        int blocks = (int)((threads + 255) / 256);
        scatter_kernel<<<blocks, 256>>>(edge_feat, recv_idx);
    }
    // 3. GEMM + bias
    {
        int blocks = (N_NODES + NT - 1) / NT;
        gemm_kernel<<<blocks, 256>>>(node_feat, W, b, out);
    }
}